// round 10
// baseline (speedup 1.0000x reference)
#include <cuda_runtime.h>
#include <cuda_fp16.h>
#include <cstdint>
#include <math.h>

#define B_  2
#define S_  2048
#define H_  16
#define DH_ 64
#define D_  1024
#define M_  (B_*S_)   // 4096

// ---------------- scratch (__device__ globals; no allocation allowed) -------
__device__ __half g_xhi[M_*D_],  g_xlo[M_*D_];
__device__ __half g_qh[M_*D_];
__device__ __half g_kh[M_*D_];
__device__ __half g_vh[M_*D_];
__device__ __half g_ahi[M_*D_],  g_alo[M_*D_];
__device__ __half g_wqh[D_*D_];
__device__ __half g_wkh[D_*D_];
__device__ __half g_wvh[D_*D_];
__device__ __half g_woh[D_*D_];

// ---------------- helpers ----------------------------------------------------
__device__ __forceinline__ uint32_t smem_u32(const void* p) {
    uint32_t a;
    asm("{ .reg .u64 t; cvta.to.shared.u64 t, %1; cvt.u32.u64 %0, t; }"
        : "=r"(a) : "l"(p));
    return a;
}
__device__ __forceinline__ void cp_async16(uint32_t saddr, const void* gaddr) {
    asm volatile("cp.async.cg.shared.global [%0], [%1], 16;"
                 :: "r"(saddr), "l"(gaddr) : "memory");
}
#define CP_COMMIT() asm volatile("cp.async.commit_group;" ::: "memory")
#define CP_WAIT(n)  asm volatile("cp.async.wait_group %0;" :: "n"(n) : "memory")

__device__ __forceinline__ void ldsm_x4(uint32_t* r, uint32_t addr) {
    asm volatile("ldmatrix.sync.aligned.m8n8.x4.shared.b16 {%0,%1,%2,%3}, [%4];"
                 : "=r"(r[0]), "=r"(r[1]), "=r"(r[2]), "=r"(r[3]) : "r"(addr));
}
__device__ __forceinline__ void ldsm_x4t(uint32_t* r, uint32_t addr) {
    asm volatile("ldmatrix.sync.aligned.m8n8.x4.trans.shared.b16 {%0,%1,%2,%3}, [%4];"
                 : "=r"(r[0]), "=r"(r[1]), "=r"(r[2]), "=r"(r[3]) : "r"(addr));
}
__device__ __forceinline__ void mma_f16(float* c, const uint32_t* a, const uint32_t* b) {
    asm volatile(
        "mma.sync.aligned.m16n8k16.row.col.f32.f16.f16.f32 "
        "{%0,%1,%2,%3}, {%4,%5,%6,%7}, {%8,%9}, {%0,%1,%2,%3};"
        : "+f"(c[0]), "+f"(c[1]), "+f"(c[2]), "+f"(c[3])
        : "r"(a[0]), "r"(a[1]), "r"(a[2]), "r"(a[3]), "r"(b[0]), "r"(b[1]));
}
__device__ __forceinline__ void split2h(float x0, float x1, uint32_t& hi, uint32_t& lo) {
    __half h0 = __float2half_rn(x0);
    __half h1 = __float2half_rn(x1);
    __half l0 = __float2half_rn(x0 - __half2float(h0));
    __half l1 = __float2half_rn(x1 - __half2float(h1));
    hi = (uint32_t)__half_as_ushort(h0) | ((uint32_t)__half_as_ushort(h1) << 16);
    lo = (uint32_t)__half_as_ushort(l0) | ((uint32_t)__half_as_ushort(l1) << 16);
}
__device__ __forceinline__ uint32_t pack2h(float x0, float x1) {
    __half h0 = __float2half_rn(x0);
    __half h1 = __float2half_rn(x1);
    return (uint32_t)__half_as_ushort(h0) | ((uint32_t)__half_as_ushort(h1) << 16);
}

// ---------------- conversions --------------------------------------------------
__global__ __launch_bounds__(256) void conv_split(
    const float* __restrict__ x, __half* __restrict__ hi,
    __half* __restrict__ lo, int n4)
{
    int i = blockIdx.x * blockDim.x + threadIdx.x;
    if (i >= n4) return;
    float4 v = ((const float4*)x)[i];
    uint32_t h0, l0, h1, l1;
    split2h(v.x, v.y, h0, l0);
    split2h(v.z, v.w, h1, l1);
    uint2 ho = { h0, h1 }, loo = { l0, l1 };
    ((uint2*)hi)[i] = ho;
    ((uint2*)lo)[i] = loo;
}

// pack 4 weight matrices to single fp16 in one launch
__global__ __launch_bounds__(256) void conv_pack_w(
    const float* w0, const float* w1, const float* w2, const float* w3,
    __half* h0, __half* h1, __half* h2, __half* h3)
{
    const float* x; __half* hi;
    if      (blockIdx.y == 0) { x = w0; hi = h0; }
    else if (blockIdx.y == 1) { x = w1; hi = h1; }
    else if (blockIdx.y == 2) { x = w2; hi = h2; }
    else                      { x = w3; hi = h3; }
    int i = blockIdx.x * blockDim.x + threadIdx.x;
    if (i >= D_*D_/4) return;
    float4 v = ((const float4*)x)[i];
    uint2 ho = { pack2h(v.x, v.y), pack2h(v.z, v.w) };
    ((uint2*)hi)[i] = ho;
}

// ---------------- mma.sync 2-pass fp16 GEMM ------------------------------------
// C[M][N] = A[M][K] @ W[N][K]^T + bias.  A split hi/lo, W single fp16.
// C = Ahi*W + Alo*W  (fp32 accum).  512 threads, 16 warps (4m x 4n),
// warp tile 32x32, BK=32 halves, 4-stage cp.async pipeline, XOR-swizzled smem.
// MODE 0: f32 output.  MODE 1: fp16 single output.
#define BKH     32
#define MAT_B   (128*64)            // 8192 B per matrix per stage
#define STAGE_B (3*MAT_B)           // Ah, Al, Wh = 24576
#define NSTAGE  4
#define GEMM_SMEM (NSTAGE*STAGE_B)  // 98304

template <int MODE>
__global__ __launch_bounds__(512, 1) void gemm_mma_split(
    const __half* __restrict__ Ahi, const __half* __restrict__ Alo,
    const __half* __restrict__ Whi,
    const float* __restrict__ bias, float* __restrict__ C,
    __half* __restrict__ Ch)
{
    extern __shared__ __align__(1024) char smraw[];
    const uint32_t sb = smem_u32(smraw);

    const int tid = threadIdx.x;
    const int wid = tid >> 5;
    const int l   = tid & 31;
    const int wm  = wid & 3;
    const int wn  = wid >> 2;
    const int m0  = blockIdx.y * 128;
    const int n0  = blockIdx.x * 128;

    const int crow = tid >> 2;
    const int cch  = tid & 3;
    const uint32_t sst = (uint32_t)(crow * 64 + ((cch ^ ((crow >> 1) & 3)) << 4));
    const __half* gAh = Ahi + (size_t)(m0 + crow) * D_ + cch * 8;
    const __half* gAl = Alo + (size_t)(m0 + crow) * D_ + cch * 8;
    const __half* gWh = Whi + (size_t)(n0 + crow) * D_ + cch * 8;

    const int rA  = wm * 32 + (l & 15);
    const int xkA = (rA >> 1) & 3;
    const int cA  = l >> 4;
    const uint32_t aA_k0 = (uint32_t)(rA * 64 + ((cA       ^ xkA) << 4));
    const uint32_t aA_k1 = (uint32_t)(rA * 64 + (((cA + 2) ^ xkA) << 4));
    const int rB  = wn * 32 + (l & 7) + ((l >> 4) << 3);
    const int xkB = (rB >> 1) & 3;
    const int cB  = (l >> 3) & 1;
    const uint32_t aB_k0 = (uint32_t)(rB * 64 + ((cB       ^ xkB) << 4));
    const uint32_t aB_k1 = (uint32_t)(rB * 64 + (((cB + 2) ^ xkB) << 4));

    float acc[2][4][4];
#pragma unroll
    for (int mt = 0; mt < 2; mt++)
#pragma unroll
        for (int nt = 0; nt < 4; nt++)
#pragma unroll
            for (int e = 0; e < 4; e++) acc[mt][nt][e] = 0.f;

    const int NKT = D_ / BKH;   // 32

    auto issue_stage = [&](int s) {
        const uint32_t d = sb + (s & (NSTAGE-1)) * STAGE_B + sst;
        const int off = s * BKH;
        cp_async16(d + 0*MAT_B, gAh + off);
        cp_async16(d + 1*MAT_B, gAl + off);
        cp_async16(d + 2*MAT_B, gWh + off);
    };

    issue_stage(0); CP_COMMIT();
    issue_stage(1); CP_COMMIT();
    issue_stage(2); CP_COMMIT();

    for (int kt = 0; kt < NKT; kt++) {
        if (kt + 3 < NKT) issue_stage(kt + 3);
        CP_COMMIT();
        CP_WAIT(3);
        __syncthreads();

        const uint32_t base = sb + (kt & (NSTAGE-1)) * STAGE_B;

#pragma unroll
        for (int kk = 0; kk < 2; kk++) {
            const uint32_t aA = base + (kk ? aA_k1 : aA_k0);
            const uint32_t aB = base + (kk ? aB_k1 : aB_k0);

            uint32_t ah[2][4];
            ldsm_x4(ah[0], aA + 0*MAT_B);
            ldsm_x4(ah[1], aA + 0*MAT_B + 1024);
            uint32_t wh[2][4];
            ldsm_x4(wh[0], aB + 2*MAT_B);
            ldsm_x4(wh[1], aB + 2*MAT_B + 1024);
#pragma unroll
            for (int mt = 0; mt < 2; mt++)
#pragma unroll
                for (int nt = 0; nt < 4; nt++)
                    mma_f16(acc[mt][nt], ah[mt], &wh[nt >> 1][(nt & 1) * 2]);

            uint32_t al[2][4];
            ldsm_x4(al[0], aA + 1*MAT_B);
            ldsm_x4(al[1], aA + 1*MAT_B + 1024);
#pragma unroll
            for (int mt = 0; mt < 2; mt++)
#pragma unroll
                for (int nt = 0; nt < 4; nt++)
                    mma_f16(acc[mt][nt], al[mt], &wh[nt >> 1][(nt & 1) * 2]);
        }

        __syncthreads();
    }

    const int rbase = m0 + wm*32 + (l >> 2);
    const int cbase = n0 + wn*32 + (l & 3) * 2;
#pragma unroll
    for (int mt = 0; mt < 2; mt++) {
#pragma unroll
        for (int nt = 0; nt < 4; nt++) {
            const int col = cbase + nt * 8;
            const float b0 = bias[col], b1 = bias[col + 1];
            const size_t r0o = (size_t)(rbase + mt*16) * D_ + col;
            const size_t r1o = (size_t)(rbase + mt*16 + 8) * D_ + col;
            if (MODE == 1) {
                *(uint32_t*)(Ch + r0o) = pack2h(acc[mt][nt][0] + b0, acc[mt][nt][1] + b1);
                *(uint32_t*)(Ch + r1o) = pack2h(acc[mt][nt][2] + b0, acc[mt][nt][3] + b1);
            } else {
                float2 v0 = { acc[mt][nt][0] + b0, acc[mt][nt][1] + b1 };
                float2 v1 = { acc[mt][nt][2] + b0, acc[mt][nt][3] + b1 };
                *(float2*)(C + r0o) = v0;
                *(float2*)(C + r1o) = v1;
            }
        }
    }
}

// ---------------- fp16 single-pass flash attention ----------------------------
// 128 queries/CTA, 8 warps x 16 q-rows. Q,K,V,P all plain fp16.
// Output split to fp16 hi/lo for the 2-pass output projection.
#define AT_QP 72
#define AT_PP 136
#define oQ 0
#define oK 18432
#define oV 36864
#define oP 55296
#define oM 90112
#define ATT_SMEM (oM + S_*4)   // 98304

__global__ __launch_bounds__(256, 2) void attn_mma(
    const __half* __restrict__ Qh, const __half* __restrict__ Kh,
    const __half* __restrict__ Vh, const int* __restrict__ mask,
    __half* __restrict__ Ah, __half* __restrict__ Al)
{
    extern __shared__ __align__(1024) char sm[];
    const uint32_t sb = smem_u32(sm);
    float* Mskf = (float*)(sm + oM);

    const int tid = threadIdx.x;
    const int wid = tid >> 5;
    const int l   = tid & 31;
    const int b   = blockIdx.y >> 4;
    const int h   = blockIdx.y & 15;
    const int q0  = blockIdx.x * 128;

    const int crow = tid >> 1, chc = (tid & 1) * 32;
    const uint32_t cds = (uint32_t)(crow * AT_QP + chc) * 2;
    const size_t gKVrow = (size_t)(b*S_ + crow) * D_ + h*DH_ + chc;

    auto issue_K = [&](int kt) {
        const size_t g = gKVrow + (size_t)kt * 128 * D_;
#pragma unroll
        for (int j = 0; j < 4; j++)
            cp_async16(sb + oK + cds + j*16, Kh + g + j*8);
    };
    auto issue_V = [&](int kt) {
        const size_t g = gKVrow + (size_t)kt * 128 * D_;
#pragma unroll
        for (int j = 0; j < 4; j++)
            cp_async16(sb + oV + cds + j*16, Vh + g + j*8);
    };

    for (int i = tid; i < S_; i += 256)
        Mskf[i] = (float)mask[(size_t)b*S_ + i];

    {
        const size_t g = (size_t)(b*S_ + q0 + crow) * D_ + h*DH_ + chc;
#pragma unroll
        for (int j = 0; j < 4; j++)
            cp_async16(sb + oQ + cds + j*16, Qh + g + j*8);
    }
    issue_K(0);
    CP_COMMIT();
    issue_V(0);
    CP_COMMIT();

    float m_run[2] = { -1e30f, -1e30f };
    float l_run[2] = { 0.f, 0.f };
    float o[8][4];
#pragma unroll
    for (int nt = 0; nt < 8; nt++)
#pragma unroll
        for (int e = 0; e < 4; e++) o[nt][e] = 0.f;

    const uint32_t aQ  = sb + oQ + (uint32_t)(((wid<<4) + (l & 15)) * AT_QP + ((l >> 4) << 3)) * 2;
    const uint32_t aKo = (uint32_t)(((l & 7) + ((l >> 4) << 3)) * AT_QP + (((l >> 3) & 1) << 3)) * 2;
    const uint32_t aP  = sb + oP + (uint32_t)(((wid<<4) + (l & 15)) * AT_PP + ((l >> 4) << 3)) * 2;
    const uint32_t aVo = (uint32_t)(((l & 7) + (((l >> 3) & 1) << 3)) * AT_QP + ((l >> 4) << 3)) * 2;

    const int r0 = l >> 2;
    const int c0 = (l & 3) * 2;

    for (int kt = 0; kt < S_/128; kt++) {
        CP_WAIT(1);            // K_kt (+Q first iter) ready
        __syncthreads();

        // ---- QK^T (single pass): s[16][4] ----
        float s[16][4];
#pragma unroll
        for (int nt = 0; nt < 16; nt++)
#pragma unroll
            for (int e = 0; e < 4; e++) s[nt][e] = 0.f;

#pragma unroll
        for (int ks = 0; ks < 4; ks++) {
            uint32_t q[4];
            ldsm_x4(q, aQ + ks*32);
#pragma unroll
            for (int np = 0; np < 8; np++) {
                uint32_t k[4];
                ldsm_x4(k, sb + oK + aKo + np*(16*AT_QP*2) + ks*32);
                mma_f16(s[2*np],   q, k);
                mma_f16(s[2*np+1], q, k+2);
            }
        }

        // ---- mask + scale + online softmax ----
        const int kb = kt * 128;
        float mx0 = -1e30f, mx1 = -1e30f;
#pragma unroll
        for (int nt = 0; nt < 16; nt++) {
            const float k0 = Mskf[kb + nt*8 + c0];
            const float k1 = Mskf[kb + nt*8 + c0 + 1];
            s[nt][0] = (k0 != 0.f) ? s[nt][0] * 0.125f : -1e30f;
            s[nt][1] = (k1 != 0.f) ? s[nt][1] * 0.125f : -1e30f;
            s[nt][2] = (k0 != 0.f) ? s[nt][2] * 0.125f : -1e30f;
            s[nt][3] = (k1 != 0.f) ? s[nt][3] * 0.125f : -1e30f;
            mx0 = fmaxf(mx0, fmaxf(s[nt][0], s[nt][1]));
            mx1 = fmaxf(mx1, fmaxf(s[nt][2], s[nt][3]));
        }
        mx0 = fmaxf(mx0, __shfl_xor_sync(0xffffffffu, mx0, 1));
        mx0 = fmaxf(mx0, __shfl_xor_sync(0xffffffffu, mx0, 2));
        mx1 = fmaxf(mx1, __shfl_xor_sync(0xffffffffu, mx1, 1));
        mx1 = fmaxf(mx1, __shfl_xor_sync(0xffffffffu, mx1, 2));

        const float mn0 = fmaxf(m_run[0], mx0);
        const float mn1 = fmaxf(m_run[1], mx1);
        const float al0 = __expf(m_run[0] - mn0);
        const float al1 = __expf(m_run[1] - mn1);
        m_run[0] = mn0; m_run[1] = mn1;

        float su0 = 0.f, su1 = 0.f;
#pragma unroll
        for (int nt = 0; nt < 16; nt++) {
            s[nt][0] = __expf(s[nt][0] - mn0);
            s[nt][1] = __expf(s[nt][1] - mn0);
            s[nt][2] = __expf(s[nt][2] - mn1);
            s[nt][3] = __expf(s[nt][3] - mn1);
            su0 += s[nt][0] + s[nt][1];
            su1 += s[nt][2] + s[nt][3];
        }
        su0 += __shfl_xor_sync(0xffffffffu, su0, 1);
        su0 += __shfl_xor_sync(0xffffffffu, su0, 2);
        su1 += __shfl_xor_sync(0xffffffffu, su1, 1);
        su1 += __shfl_xor_sync(0xffffffffu, su1, 2);
        l_run[0] = l_run[0] * al0 + su0;
        l_run[1] = l_run[1] * al1 + su1;

#pragma unroll
        for (int nt = 0; nt < 8; nt++) {
            o[nt][0] *= al0; o[nt][1] *= al0;
            o[nt][2] *= al1; o[nt][3] *= al1;
        }

        // ---- store P (fp16) ----
        {
            char* p0 = sm + oP + (size_t)(((wid<<4) + r0) * AT_PP + c0) * 2;
            char* p1 = p0 + 8 * AT_PP * 2;
#pragma unroll
            for (int nt = 0; nt < 16; nt++) {
                *(uint32_t*)(p0 + nt*16) = pack2h(s[nt][0], s[nt][1]);
                *(uint32_t*)(p1 + nt*16) = pack2h(s[nt][2], s[nt][3]);
            }
        }

        CP_WAIT(0);            // V_kt arrived
        __syncthreads();       // P visible; K_kt reads done

        if (kt + 1 < S_/128) issue_K(kt + 1);   // overlaps PV
        CP_COMMIT();

        // ---- PV (single pass) ----
#pragma unroll
        for (int ks = 0; ks < 8; ks++) {
            uint32_t p[4];
            ldsm_x4(p, aP + ks*32);
#pragma unroll
            for (int vb = 0; vb < 4; vb++) {
                uint32_t v[4];
                ldsm_x4t(v, sb + oV + aVo + ks*(16*AT_QP*2) + vb*32);
                mma_f16(o[2*vb],   p, v);
                mma_f16(o[2*vb+1], p, v+2);
            }
        }

        __syncthreads();       // V_kt reads done
        if (kt + 1 < S_/128) issue_V(kt + 1);   // overlaps next QK
        CP_COMMIT();
    }

    // ---- epilogue: normalize, split to fp16 hi/lo ----
    const float i0 = 1.f / l_run[0];
    const float i1 = 1.f / l_run[1];
    const size_t row0 = (size_t)(b*S_ + q0 + (wid<<4) + r0);
    const size_t row1 = row0 + 8;
#pragma unroll
    for (int nt = 0; nt < 8; nt++) {
        const int col = h*DH_ + nt*8 + c0;
        uint32_t hi, lo;
        split2h(o[nt][0]*i0, o[nt][1]*i0, hi, lo);
        *(uint32_t*)(Ah + row0*D_ + col) = hi;
        *(uint32_t*)(Al + row0*D_ + col) = lo;
        split2h(o[nt][2]*i1, o[nt][3]*i1, hi, lo);
        *(uint32_t*)(Ah + row1*D_ + col) = hi;
        *(uint32_t*)(Al + row1*D_ + col) = lo;
    }
}

// ---------------------------------------------------------------------------
extern "C" void kernel_launch(void* const* d_in, const int* in_sizes, int n_in,
                              void* d_out, int out_size)
{
    const float* x    = (const float*)d_in[0];
    const int*   mask = (const int*)  d_in[1];
    const float* Wq   = (const float*)d_in[2];
    const float* bq   = (const float*)d_in[3];
    const float* Wk   = (const float*)d_in[4];
    const float* bk   = (const float*)d_in[5];
    const float* Wv   = (const float*)d_in[6];
    const float* bv   = (const float*)d_in[7];
    const float* Wo   = (const float*)d_in[8];
    const float* bo   = (const float*)d_in[9];
    float* out = (float*)d_out;

    __half *xhi, *xlo, *qh, *kh, *vh, *ahi, *alo;
    __half *wqh, *wkh, *wvh, *woh;
    cudaGetSymbolAddress((void**)&xhi, g_xhi);
    cudaGetSymbolAddress((void**)&xlo, g_xlo);
    cudaGetSymbolAddress((void**)&qh,  g_qh);
    cudaGetSymbolAddress((void**)&kh,  g_kh);
    cudaGetSymbolAddress((void**)&vh,  g_vh);
    cudaGetSymbolAddress((void**)&ahi, g_ahi);
    cudaGetSymbolAddress((void**)&alo, g_alo);
    cudaGetSymbolAddress((void**)&wqh, g_wqh);
    cudaGetSymbolAddress((void**)&wkh, g_wkh);
    cudaGetSymbolAddress((void**)&wvh, g_wvh);
    cudaGetSymbolAddress((void**)&woh, g_woh);

    cudaFuncSetAttribute(gemm_mma_split<0>,
                         cudaFuncAttributeMaxDynamicSharedMemorySize, GEMM_SMEM);
    cudaFuncSetAttribute(gemm_mma_split<1>,
                         cudaFuncAttributeMaxDynamicSharedMemorySize, GEMM_SMEM);
    cudaFuncSetAttribute(attn_mma,
                         cudaFuncAttributeMaxDynamicSharedMemorySize, ATT_SMEM);

    conv_split<<<(M_*D_/4)/256, 256>>>(x, xhi, xlo, M_*D_/4);
    dim3 gw((D_*D_/4)/256, 4);
    conv_pack_w<<<gw, 256>>>(Wq, Wk, Wv, Wo, wqh, wkh, wvh, woh);

    dim3 gg(D_/128, M_/128);   // (8, 32)
    gemm_mma_split<1><<<gg, 512, GEMM_SMEM>>>(xhi, xlo, wqh, bq, nullptr, qh);
    gemm_mma_split<1><<<gg, 512, GEMM_SMEM>>>(xhi, xlo, wkh, bk, nullptr, kh);
    gemm_mma_split<1><<<gg, 512, GEMM_SMEM>>>(xhi, xlo, wvh, bv, nullptr, vh);

    dim3 ga(S_/128, B_*H_);    // (16, 32)
    attn_mma<<<ga, 256, ATT_SMEM>>>(qh, kh, vh, mask, ahi, alo);

    gemm_mma_split<0><<<gg, 512, GEMM_SMEM>>>(ahi, alo, woh, bo, out, nullptr);
}

// round 11
// speedup vs baseline: 1.2723x; 1.2723x over previous
#include <cuda_runtime.h>
#include <cuda_fp16.h>
#include <cstdint>
#include <math.h>

#define B_  2
#define S_  2048
#define H_  16
#define DH_ 64
#define D_  1024
#define M_  (B_*S_)   // 4096

// ---------------- scratch (__device__ globals; no allocation allowed) -------
__device__ __half g_xhi[M_*D_],  g_xlo[M_*D_];
__device__ __half g_qh[M_*D_];
__device__ __half g_kh[M_*D_];
__device__ __half g_vh[M_*D_];
__device__ __half g_ahi[M_*D_],  g_alo[M_*D_];
__device__ __half g_wqhi[D_*D_], g_wqlo[D_*D_];
__device__ __half g_wkhi[D_*D_], g_wklo[D_*D_];
__device__ __half g_wvhi[D_*D_], g_wvlo[D_*D_];
__device__ __half g_wohi[D_*D_], g_wolo[D_*D_];

// ---------------- helpers ----------------------------------------------------
__device__ __forceinline__ uint32_t smem_u32(const void* p) {
    uint32_t a;
    asm("{ .reg .u64 t; cvta.to.shared.u64 t, %1; cvt.u32.u64 %0, t; }"
        : "=r"(a) : "l"(p));
    return a;
}
__device__ __forceinline__ void cp_async16(uint32_t saddr, const void* gaddr) {
    asm volatile("cp.async.cg.shared.global [%0], [%1], 16;"
                 :: "r"(saddr), "l"(gaddr) : "memory");
}
#define CP_COMMIT() asm volatile("cp.async.commit_group;" ::: "memory")
#define CP_WAIT(n)  asm volatile("cp.async.wait_group %0;" :: "n"(n) : "memory")

__device__ __forceinline__ void ldsm_x4(uint32_t* r, uint32_t addr) {
    asm volatile("ldmatrix.sync.aligned.m8n8.x4.shared.b16 {%0,%1,%2,%3}, [%4];"
                 : "=r"(r[0]), "=r"(r[1]), "=r"(r[2]), "=r"(r[3]) : "r"(addr));
}
__device__ __forceinline__ void ldsm_x4t(uint32_t* r, uint32_t addr) {
    asm volatile("ldmatrix.sync.aligned.m8n8.x4.trans.shared.b16 {%0,%1,%2,%3}, [%4];"
                 : "=r"(r[0]), "=r"(r[1]), "=r"(r[2]), "=r"(r[3]) : "r"(addr));
}
__device__ __forceinline__ void mma_f16(float* c, const uint32_t* a, const uint32_t* b) {
    asm volatile(
        "mma.sync.aligned.m16n8k16.row.col.f32.f16.f16.f32 "
        "{%0,%1,%2,%3}, {%4,%5,%6,%7}, {%8,%9}, {%0,%1,%2,%3};"
        : "+f"(c[0]), "+f"(c[1]), "+f"(c[2]), "+f"(c[3])
        : "r"(a[0]), "r"(a[1]), "r"(a[2]), "r"(a[3]), "r"(b[0]), "r"(b[1]));
}
__device__ __forceinline__ void split2h(float x0, float x1, uint32_t& hi, uint32_t& lo) {
    __half h0 = __float2half_rn(x0);
    __half h1 = __float2half_rn(x1);
    __half l0 = __float2half_rn(x0 - __half2float(h0));
    __half l1 = __float2half_rn(x1 - __half2float(h1));
    hi = (uint32_t)__half_as_ushort(h0) | ((uint32_t)__half_as_ushort(h1) << 16);
    lo = (uint32_t)__half_as_ushort(l0) | ((uint32_t)__half_as_ushort(l1) << 16);
}
__device__ __forceinline__ uint32_t pack2h(float x0, float x1) {
    __half h0 = __float2half_rn(x0);
    __half h1 = __float2half_rn(x1);
    return (uint32_t)__half_as_ushort(h0) | ((uint32_t)__half_as_ushort(h1) << 16);
}

// ---------------- conversions --------------------------------------------------
__global__ __launch_bounds__(256) void conv_split(
    const float* __restrict__ x, __half* __restrict__ hi,
    __half* __restrict__ lo, int n4)
{
    int i = blockIdx.x * blockDim.x + threadIdx.x;
    if (i >= n4) return;
    float4 v = ((const float4*)x)[i];
    uint32_t h0, l0, h1, l1;
    split2h(v.x, v.y, h0, l0);
    split2h(v.z, v.w, h1, l1);
    uint2 ho = { h0, h1 }, loo = { l0, l1 };
    ((uint2*)hi)[i] = ho;
    ((uint2*)lo)[i] = loo;
}

// split all 4 weight matrices (hi/lo) in one launch
__global__ __launch_bounds__(256) void conv_split_w(
    const float* w0, const float* w1, const float* w2, const float* w3,
    __half* h0, __half* l0, __half* h1, __half* l1,
    __half* h2, __half* l2, __half* h3, __half* l3)
{
    const float* x; __half* hi; __half* lo;
    if      (blockIdx.y == 0) { x = w0; hi = h0; lo = l0; }
    else if (blockIdx.y == 1) { x = w1; hi = h1; lo = l1; }
    else if (blockIdx.y == 2) { x = w2; hi = h2; lo = l2; }
    else                      { x = w3; hi = h3; lo = l3; }
    int i = blockIdx.x * blockDim.x + threadIdx.x;
    if (i >= D_*D_/4) return;
    float4 v = ((const float4*)x)[i];
    uint32_t a0, b0, a1, b1;
    split2h(v.x, v.y, a0, b0);
    split2h(v.z, v.w, a1, b1);
    uint2 ho = { a0, a1 }, loo = { b0, b1 };
    ((uint2*)hi)[i] = ho;
    ((uint2*)lo)[i] = loo;
}

// ---------------- mma.sync 3-pass fp16 GEMM (R9 config, z-fused) ---------------
// C[M][N] = A[M][K] @ W[N][K]^T + bias.  A and W split hi/lo.
// C = Ahi*Whi + Ahi*Wlo + Alo*Whi  (fp32 accum).
// 512 threads, 16 warps (4m x 4n), warp 32x32, BK=32 halves, 4-stage cp.async,
// XOR-swizzled smem. blockIdx.z selects (W, bias, output) -> QKV in ONE launch.
// MODE 0: f32 output (z=0 only).  MODE 1: fp16 output.
#define BKH     32
#define MAT_B   (128*64)
#define STAGE_B (4*MAT_B)           // Ah, Al, Wh, Wl = 32768
#define NSTAGE  4
#define GEMM_SMEM (NSTAGE*STAGE_B)  // 131072

template <int MODE>
__global__ __launch_bounds__(512, 1) void gemm_mma_split(
    const __half* __restrict__ Ahi, const __half* __restrict__ Alo,
    const __half* __restrict__ Wh0, const __half* __restrict__ Wl0,
    const __half* __restrict__ Wh1, const __half* __restrict__ Wl1,
    const __half* __restrict__ Wh2, const __half* __restrict__ Wl2,
    const float* __restrict__ b0p, const float* __restrict__ b1p,
    const float* __restrict__ b2p,
    float* __restrict__ C,
    __half* __restrict__ C0, __half* __restrict__ C1, __half* __restrict__ C2)
{
    const __half* Whi; const __half* Wlo; const float* bias; __half* Ch;
    if      (blockIdx.z == 0) { Whi = Wh0; Wlo = Wl0; bias = b0p; Ch = C0; }
    else if (blockIdx.z == 1) { Whi = Wh1; Wlo = Wl1; bias = b1p; Ch = C1; }
    else                      { Whi = Wh2; Wlo = Wl2; bias = b2p; Ch = C2; }

    extern __shared__ __align__(1024) char smraw[];
    const uint32_t sb = smem_u32(smraw);

    const int tid = threadIdx.x;
    const int wid = tid >> 5;
    const int l   = tid & 31;
    const int wm  = wid & 3;
    const int wn  = wid >> 2;
    const int m0  = blockIdx.y * 128;
    const int n0  = blockIdx.x * 128;

    const int crow = tid >> 2;
    const int cch  = tid & 3;
    const uint32_t sst = (uint32_t)(crow * 64 + ((cch ^ ((crow >> 1) & 3)) << 4));
    const __half* gAh = Ahi + (size_t)(m0 + crow) * D_ + cch * 8;
    const __half* gAl = Alo + (size_t)(m0 + crow) * D_ + cch * 8;
    const __half* gWh = Whi + (size_t)(n0 + crow) * D_ + cch * 8;
    const __half* gWl = Wlo + (size_t)(n0 + crow) * D_ + cch * 8;

    const int rA  = wm * 32 + (l & 15);
    const int xkA = (rA >> 1) & 3;
    const int cA  = l >> 4;
    const uint32_t aA_k0 = (uint32_t)(rA * 64 + ((cA       ^ xkA) << 4));
    const uint32_t aA_k1 = (uint32_t)(rA * 64 + (((cA + 2) ^ xkA) << 4));
    const int rB  = wn * 32 + (l & 7) + ((l >> 4) << 3);
    const int xkB = (rB >> 1) & 3;
    const int cB  = (l >> 3) & 1;
    const uint32_t aB_k0 = (uint32_t)(rB * 64 + ((cB       ^ xkB) << 4));
    const uint32_t aB_k1 = (uint32_t)(rB * 64 + (((cB + 2) ^ xkB) << 4));

    float acc[2][4][4];
#pragma unroll
    for (int mt = 0; mt < 2; mt++)
#pragma unroll
        for (int nt = 0; nt < 4; nt++)
#pragma unroll
            for (int e = 0; e < 4; e++) acc[mt][nt][e] = 0.f;

    const int NKT = D_ / BKH;   // 32

    auto issue_stage = [&](int s) {
        const uint32_t d = sb + (s & (NSTAGE-1)) * STAGE_B + sst;
        const int off = s * BKH;
        cp_async16(d + 0*MAT_B, gAh + off);
        cp_async16(d + 1*MAT_B, gAl + off);
        cp_async16(d + 2*MAT_B, gWh + off);
        cp_async16(d + 3*MAT_B, gWl + off);
    };

    issue_stage(0); CP_COMMIT();
    issue_stage(1); CP_COMMIT();
    issue_stage(2); CP_COMMIT();

    for (int kt = 0; kt < NKT; kt++) {
        if (kt + 3 < NKT) issue_stage(kt + 3);
        CP_COMMIT();
        CP_WAIT(3);
        __syncthreads();

        const uint32_t base = sb + (kt & (NSTAGE-1)) * STAGE_B;

#pragma unroll
        for (int kk = 0; kk < 2; kk++) {
            const uint32_t aA = base + (kk ? aA_k1 : aA_k0);
            const uint32_t aB = base + (kk ? aB_k1 : aB_k0);

            uint32_t ah[2][4];
            ldsm_x4(ah[0], aA + 0*MAT_B);
            ldsm_x4(ah[1], aA + 0*MAT_B + 1024);
            uint32_t wh[2][4];
            ldsm_x4(wh[0], aB + 2*MAT_B);
            ldsm_x4(wh[1], aB + 2*MAT_B + 1024);
#pragma unroll
            for (int mt = 0; mt < 2; mt++)
#pragma unroll
                for (int nt = 0; nt < 4; nt++)
                    mma_f16(acc[mt][nt], ah[mt], &wh[nt >> 1][(nt & 1) * 2]);

            uint32_t wl[2][4];
            ldsm_x4(wl[0], aB + 3*MAT_B);
            ldsm_x4(wl[1], aB + 3*MAT_B + 1024);
#pragma unroll
            for (int mt = 0; mt < 2; mt++)
#pragma unroll
                for (int nt = 0; nt < 4; nt++)
                    mma_f16(acc[mt][nt], ah[mt], &wl[nt >> 1][(nt & 1) * 2]);

            uint32_t al[2][4];
            ldsm_x4(al[0], aA + 1*MAT_B);
            ldsm_x4(al[1], aA + 1*MAT_B + 1024);
#pragma unroll
            for (int mt = 0; mt < 2; mt++)
#pragma unroll
                for (int nt = 0; nt < 4; nt++)
                    mma_f16(acc[mt][nt], al[mt], &wh[nt >> 1][(nt & 1) * 2]);
        }

        __syncthreads();
    }

    const int rbase = m0 + wm*32 + (l >> 2);
    const int cbase = n0 + wn*32 + (l & 3) * 2;
#pragma unroll
    for (int mt = 0; mt < 2; mt++) {
#pragma unroll
        for (int nt = 0; nt < 4; nt++) {
            const int col = cbase + nt * 8;
            const float b0 = bias[col], b1 = bias[col + 1];
            const size_t r0o = (size_t)(rbase + mt*16) * D_ + col;
            const size_t r1o = (size_t)(rbase + mt*16 + 8) * D_ + col;
            if (MODE == 1) {
                *(uint32_t*)(Ch + r0o) = pack2h(acc[mt][nt][0] + b0, acc[mt][nt][1] + b1);
                *(uint32_t*)(Ch + r1o) = pack2h(acc[mt][nt][2] + b0, acc[mt][nt][3] + b1);
            } else {
                float2 v0 = { acc[mt][nt][0] + b0, acc[mt][nt][1] + b1 };
                float2 v1 = { acc[mt][nt][2] + b0, acc[mt][nt][3] + b1 };
                *(float2*)(C + r0o) = v0;
                *(float2*)(C + r1o) = v1;
            }
        }
    }
}

// ---------------- fp16 single-pass flash attention (R9, unchanged) -------------
#define AT_QP 72
#define AT_PP 136
#define oQ 0
#define oK 18432
#define oV 36864
#define oP 55296
#define oM 90112
#define ATT_SMEM (oM + S_*4)   // 98304

__global__ __launch_bounds__(256, 2) void attn_mma(
    const __half* __restrict__ Qh, const __half* __restrict__ Kh,
    const __half* __restrict__ Vh, const int* __restrict__ mask,
    __half* __restrict__ Ah, __half* __restrict__ Al)
{
    extern __shared__ __align__(1024) char sm[];
    const uint32_t sb = smem_u32(sm);
    float* Mskf = (float*)(sm + oM);

    const int tid = threadIdx.x;
    const int wid = tid >> 5;
    const int l   = tid & 31;
    const int b   = blockIdx.y >> 4;
    const int h   = blockIdx.y & 15;
    const int q0  = blockIdx.x * 128;

    const int crow = tid >> 1, chc = (tid & 1) * 32;
    const uint32_t cds = (uint32_t)(crow * AT_QP + chc) * 2;
    const size_t gKVrow = (size_t)(b*S_ + crow) * D_ + h*DH_ + chc;

    auto issue_K = [&](int kt) {
        const size_t g = gKVrow + (size_t)kt * 128 * D_;
#pragma unroll
        for (int j = 0; j < 4; j++)
            cp_async16(sb + oK + cds + j*16, Kh + g + j*8);
    };
    auto issue_V = [&](int kt) {
        const size_t g = gKVrow + (size_t)kt * 128 * D_;
#pragma unroll
        for (int j = 0; j < 4; j++)
            cp_async16(sb + oV + cds + j*16, Vh + g + j*8);
    };

    for (int i = tid; i < S_; i += 256)
        Mskf[i] = (float)mask[(size_t)b*S_ + i];

    {
        const size_t g = (size_t)(b*S_ + q0 + crow) * D_ + h*DH_ + chc;
#pragma unroll
        for (int j = 0; j < 4; j++)
            cp_async16(sb + oQ + cds + j*16, Qh + g + j*8);
    }
    issue_K(0);
    CP_COMMIT();
    issue_V(0);
    CP_COMMIT();

    float m_run[2] = { -1e30f, -1e30f };
    float l_run[2] = { 0.f, 0.f };
    float o[8][4];
#pragma unroll
    for (int nt = 0; nt < 8; nt++)
#pragma unroll
        for (int e = 0; e < 4; e++) o[nt][e] = 0.f;

    const uint32_t aQ  = sb + oQ + (uint32_t)(((wid<<4) + (l & 15)) * AT_QP + ((l >> 4) << 3)) * 2;
    const uint32_t aKo = (uint32_t)(((l & 7) + ((l >> 4) << 3)) * AT_QP + (((l >> 3) & 1) << 3)) * 2;
    const uint32_t aP  = sb + oP + (uint32_t)(((wid<<4) + (l & 15)) * AT_PP + ((l >> 4) << 3)) * 2;
    const uint32_t aVo = (uint32_t)(((l & 7) + (((l >> 3) & 1) << 3)) * AT_QP + ((l >> 4) << 3)) * 2;

    const int r0 = l >> 2;
    const int c0 = (l & 3) * 2;

    for (int kt = 0; kt < S_/128; kt++) {
        CP_WAIT(1);
        __syncthreads();

        // ---- QK^T (single pass) ----
        float s[16][4];
#pragma unroll
        for (int nt = 0; nt < 16; nt++)
#pragma unroll
            for (int e = 0; e < 4; e++) s[nt][e] = 0.f;

#pragma unroll
        for (int ks = 0; ks < 4; ks++) {
            uint32_t q[4];
            ldsm_x4(q, aQ + ks*32);
#pragma unroll
            for (int np = 0; np < 8; np++) {
                uint32_t k[4];
                ldsm_x4(k, sb + oK + aKo + np*(16*AT_QP*2) + ks*32);
                mma_f16(s[2*np],   q, k);
                mma_f16(s[2*np+1], q, k+2);
            }
        }

        // ---- mask + scale + online softmax ----
        const int kb = kt * 128;
        float mx0 = -1e30f, mx1 = -1e30f;
#pragma unroll
        for (int nt = 0; nt < 16; nt++) {
            const float k0 = Mskf[kb + nt*8 + c0];
            const float k1 = Mskf[kb + nt*8 + c0 + 1];
            s[nt][0] = (k0 != 0.f) ? s[nt][0] * 0.125f : -1e30f;
            s[nt][1] = (k1 != 0.f) ? s[nt][1] * 0.125f : -1e30f;
            s[nt][2] = (k0 != 0.f) ? s[nt][2] * 0.125f : -1e30f;
            s[nt][3] = (k1 != 0.f) ? s[nt][3] * 0.125f : -1e30f;
            mx0 = fmaxf(mx0, fmaxf(s[nt][0], s[nt][1]));
            mx1 = fmaxf(mx1, fmaxf(s[nt][2], s[nt][3]));
        }
        mx0 = fmaxf(mx0, __shfl_xor_sync(0xffffffffu, mx0, 1));
        mx0 = fmaxf(mx0, __shfl_xor_sync(0xffffffffu, mx0, 2));
        mx1 = fmaxf(mx1, __shfl_xor_sync(0xffffffffu, mx1, 1));
        mx1 = fmaxf(mx1, __shfl_xor_sync(0xffffffffu, mx1, 2));

        const float mn0 = fmaxf(m_run[0], mx0);
        const float mn1 = fmaxf(m_run[1], mx1);
        const float al0 = __expf(m_run[0] - mn0);
        const float al1 = __expf(m_run[1] - mn1);
        m_run[0] = mn0; m_run[1] = mn1;

        float su0 = 0.f, su1 = 0.f;
#pragma unroll
        for (int nt = 0; nt < 16; nt++) {
            s[nt][0] = __expf(s[nt][0] - mn0);
            s[nt][1] = __expf(s[nt][1] - mn0);
            s[nt][2] = __expf(s[nt][2] - mn1);
            s[nt][3] = __expf(s[nt][3] - mn1);
            su0 += s[nt][0] + s[nt][1];
            su1 += s[nt][2] + s[nt][3];
        }
        su0 += __shfl_xor_sync(0xffffffffu, su0, 1);
        su0 += __shfl_xor_sync(0xffffffffu, su0, 2);
        su1 += __shfl_xor_sync(0xffffffffu, su1, 1);
        su1 += __shfl_xor_sync(0xffffffffu, su1, 2);
        l_run[0] = l_run[0] * al0 + su0;
        l_run[1] = l_run[1] * al1 + su1;

#pragma unroll
        for (int nt = 0; nt < 8; nt++) {
            o[nt][0] *= al0; o[nt][1] *= al0;
            o[nt][2] *= al1; o[nt][3] *= al1;
        }

        // ---- store P (fp16) ----
        {
            char* p0 = sm + oP + (size_t)(((wid<<4) + r0) * AT_PP + c0) * 2;
            char* p1 = p0 + 8 * AT_PP * 2;
#pragma unroll
            for (int nt = 0; nt < 16; nt++) {
                *(uint32_t*)(p0 + nt*16) = pack2h(s[nt][0], s[nt][1]);
                *(uint32_t*)(p1 + nt*16) = pack2h(s[nt][2], s[nt][3]);
            }
        }

        CP_WAIT(0);
        __syncthreads();

        if (kt + 1 < S_/128) issue_K(kt + 1);
        CP_COMMIT();

        // ---- PV (single pass) ----
#pragma unroll
        for (int ks = 0; ks < 8; ks++) {
            uint32_t p[4];
            ldsm_x4(p, aP + ks*32);
#pragma unroll
            for (int vb = 0; vb < 4; vb++) {
                uint32_t v[4];
                ldsm_x4t(v, sb + oV + aVo + ks*(16*AT_QP*2) + vb*32);
                mma_f16(o[2*vb],   p, v);
                mma_f16(o[2*vb+1], p, v+2);
            }
        }

        __syncthreads();
        if (kt + 1 < S_/128) issue_V(kt + 1);
        CP_COMMIT();
    }

    // ---- epilogue: normalize, split to fp16 hi/lo ----
    const float i0 = 1.f / l_run[0];
    const float i1 = 1.f / l_run[1];
    const size_t row0 = (size_t)(b*S_ + q0 + (wid<<4) + r0);
    const size_t row1 = row0 + 8;
#pragma unroll
    for (int nt = 0; nt < 8; nt++) {
        const int col = h*DH_ + nt*8 + c0;
        uint32_t hi, lo;
        split2h(o[nt][0]*i0, o[nt][1]*i0, hi, lo);
        *(uint32_t*)(Ah + row0*D_ + col) = hi;
        *(uint32_t*)(Al + row0*D_ + col) = lo;
        split2h(o[nt][2]*i1, o[nt][3]*i1, hi, lo);
        *(uint32_t*)(Ah + row1*D_ + col) = hi;
        *(uint32_t*)(Al + row1*D_ + col) = lo;
    }
}

// ---------------------------------------------------------------------------
extern "C" void kernel_launch(void* const* d_in, const int* in_sizes, int n_in,
                              void* d_out, int out_size)
{
    const float* x    = (const float*)d_in[0];
    const int*   mask = (const int*)  d_in[1];
    const float* Wq   = (const float*)d_in[2];
    const float* bq   = (const float*)d_in[3];
    const float* Wk   = (const float*)d_in[4];
    const float* bk   = (const float*)d_in[5];
    const float* Wv   = (const float*)d_in[6];
    const float* bv   = (const float*)d_in[7];
    const float* Wo   = (const float*)d_in[8];
    const float* bo   = (const float*)d_in[9];
    float* out = (float*)d_out;

    __half *xhi, *xlo, *qh, *kh, *vh, *ahi, *alo;
    __half *wqh, *wql, *wkh, *wkl, *wvh, *wvl, *woh, *wol;
    cudaGetSymbolAddress((void**)&xhi, g_xhi);
    cudaGetSymbolAddress((void**)&xlo, g_xlo);
    cudaGetSymbolAddress((void**)&qh,  g_qh);
    cudaGetSymbolAddress((void**)&kh,  g_kh);
    cudaGetSymbolAddress((void**)&vh,  g_vh);
    cudaGetSymbolAddress((void**)&ahi, g_ahi);
    cudaGetSymbolAddress((void**)&alo, g_alo);
    cudaGetSymbolAddress((void**)&wqh, g_wqhi);
    cudaGetSymbolAddress((void**)&wql, g_wqlo);
    cudaGetSymbolAddress((void**)&wkh, g_wkhi);
    cudaGetSymbolAddress((void**)&wkl, g_wklo);
    cudaGetSymbolAddress((void**)&wvh, g_wvhi);
    cudaGetSymbolAddress((void**)&wvl, g_wvlo);
    cudaGetSymbolAddress((void**)&woh, g_wohi);
    cudaGetSymbolAddress((void**)&wol, g_wolo);

    cudaFuncSetAttribute(gemm_mma_split<0>,
                         cudaFuncAttributeMaxDynamicSharedMemorySize, GEMM_SMEM);
    cudaFuncSetAttribute(gemm_mma_split<1>,
                         cudaFuncAttributeMaxDynamicSharedMemorySize, GEMM_SMEM);
    cudaFuncSetAttribute(attn_mma,
                         cudaFuncAttributeMaxDynamicSharedMemorySize, ATT_SMEM);

    conv_split<<<(M_*D_/4)/256, 256>>>(x, xhi, xlo, M_*D_/4);
    dim3 gw((D_*D_/4)/256, 4);
    conv_split_w<<<gw, 256>>>(Wq, Wk, Wv, Wo,
                              wqh, wql, wkh, wkl, wvh, wvl, woh, wol);

    // fused QKV: one launch, blockIdx.z selects projection
    dim3 gq(D_/128, M_/128, 3);   // (8, 32, 3)
    gemm_mma_split<1><<<gq, 512, GEMM_SMEM>>>(
        xhi, xlo,
        wqh, wql, wkh, wkl, wvh, wvl,
        bq, bk, bv,
        nullptr, qh, kh, vh);

    dim3 ga(S_/128, B_*H_);    // (16, 32)
    attn_mma<<<ga, 256, ATT_SMEM>>>(qh, kh, vh, mask, ahi, alo);

    dim3 gg(D_/128, M_/128, 1);
    gemm_mma_split<0><<<gg, 512, GEMM_SMEM>>>(
        ahi, alo,
        woh, wol, woh, wol, woh, wol,
        bo, bo, bo,
        out, nullptr, nullptr, nullptr);
}

// round 12
// speedup vs baseline: 1.3107x; 1.0302x over previous
#include <cuda_runtime.h>
#include <cuda_fp16.h>
#include <cstdint>
#include <math.h>

#define B_  2
#define S_  2048
#define H_  16
#define DH_ 64
#define D_  1024
#define M_  (B_*S_)   // 4096

// ---------------- scratch (__device__ globals; no allocation allowed) -------
__device__ __half g_xhi[M_*D_],  g_xlo[M_*D_];
__device__ __half g_qh[M_*D_];
__device__ __half g_kh[M_*D_];
__device__ __half g_vh[M_*D_];
__device__ __half g_ahi[M_*D_],  g_alo[M_*D_];
__device__ __half g_wqhi[D_*D_], g_wqlo[D_*D_];
__device__ __half g_wkhi[D_*D_], g_wklo[D_*D_];
__device__ __half g_wvhi[D_*D_], g_wvlo[D_*D_];
__device__ __half g_wohi[D_*D_], g_wolo[D_*D_];

// ---------------- helpers ----------------------------------------------------
__device__ __forceinline__ uint32_t smem_u32(const void* p) {
    uint32_t a;
    asm("{ .reg .u64 t; cvta.to.shared.u64 t, %1; cvt.u32.u64 %0, t; }"
        : "=r"(a) : "l"(p));
    return a;
}
__device__ __forceinline__ void cp_async16(uint32_t saddr, const void* gaddr) {
    asm volatile("cp.async.cg.shared.global [%0], [%1], 16;"
                 :: "r"(saddr), "l"(gaddr) : "memory");
}
#define CP_COMMIT() asm volatile("cp.async.commit_group;" ::: "memory")
#define CP_WAIT(n)  asm volatile("cp.async.wait_group %0;" :: "n"(n) : "memory")

__device__ __forceinline__ void ldsm_x4(uint32_t* r, uint32_t addr) {
    asm volatile("ldmatrix.sync.aligned.m8n8.x4.shared.b16 {%0,%1,%2,%3}, [%4];"
                 : "=r"(r[0]), "=r"(r[1]), "=r"(r[2]), "=r"(r[3]) : "r"(addr));
}
__device__ __forceinline__ void ldsm_x4t(uint32_t* r, uint32_t addr) {
    asm volatile("ldmatrix.sync.aligned.m8n8.x4.trans.shared.b16 {%0,%1,%2,%3}, [%4];"
                 : "=r"(r[0]), "=r"(r[1]), "=r"(r[2]), "=r"(r[3]) : "r"(addr));
}
__device__ __forceinline__ void mma_f16(float* c, const uint32_t* a, const uint32_t* b) {
    asm volatile(
        "mma.sync.aligned.m16n8k16.row.col.f32.f16.f16.f32 "
        "{%0,%1,%2,%3}, {%4,%5,%6,%7}, {%8,%9}, {%0,%1,%2,%3};"
        : "+f"(c[0]), "+f"(c[1]), "+f"(c[2]), "+f"(c[3])
        : "r"(a[0]), "r"(a[1]), "r"(a[2]), "r"(a[3]), "r"(b[0]), "r"(b[1]));
}
__device__ __forceinline__ float ex2f(float x) {
    float r;
    asm("ex2.approx.f32 %0, %1;" : "=f"(r) : "f"(x));
    return r;
}
__device__ __forceinline__ void split2h(float x0, float x1, uint32_t& hi, uint32_t& lo) {
    __half h0 = __float2half_rn(x0);
    __half h1 = __float2half_rn(x1);
    __half l0 = __float2half_rn(x0 - __half2float(h0));
    __half l1 = __float2half_rn(x1 - __half2float(h1));
    hi = (uint32_t)__half_as_ushort(h0) | ((uint32_t)__half_as_ushort(h1) << 16);
    lo = (uint32_t)__half_as_ushort(l0) | ((uint32_t)__half_as_ushort(l1) << 16);
}
__device__ __forceinline__ uint32_t pack2h(float x0, float x1) {
    __half h0 = __float2half_rn(x0);
    __half h1 = __float2half_rn(x1);
    return (uint32_t)__half_as_ushort(h0) | ((uint32_t)__half_as_ushort(h1) << 16);
}

// ---------------- conversions --------------------------------------------------
__global__ __launch_bounds__(256) void conv_split(
    const float* __restrict__ x, __half* __restrict__ hi,
    __half* __restrict__ lo, int n4)
{
    int i = blockIdx.x * blockDim.x + threadIdx.x;
    if (i >= n4) return;
    float4 v = ((const float4*)x)[i];
    uint32_t h0, l0, h1, l1;
    split2h(v.x, v.y, h0, l0);
    split2h(v.z, v.w, h1, l1);
    uint2 ho = { h0, h1 }, loo = { l0, l1 };
    ((uint2*)hi)[i] = ho;
    ((uint2*)lo)[i] = loo;
}

__global__ __launch_bounds__(256) void conv_split_w(
    const float* w0, const float* w1, const float* w2, const float* w3,
    __half* h0, __half* l0, __half* h1, __half* l1,
    __half* h2, __half* l2, __half* h3, __half* l3)
{
    const float* x; __half* hi; __half* lo;
    if      (blockIdx.y == 0) { x = w0; hi = h0; lo = l0; }
    else if (blockIdx.y == 1) { x = w1; hi = h1; lo = l1; }
    else if (blockIdx.y == 2) { x = w2; hi = h2; lo = l2; }
    else                      { x = w3; hi = h3; lo = l3; }
    int i = blockIdx.x * blockDim.x + threadIdx.x;
    if (i >= D_*D_/4) return;
    float4 v = ((const float4*)x)[i];
    uint32_t a0, b0, a1, b1;
    split2h(v.x, v.y, a0, b0);
    split2h(v.z, v.w, a1, b1);
    uint2 ho = { a0, a1 }, loo = { b0, b1 };
    ((uint2*)hi)[i] = ho;
    ((uint2*)lo)[i] = loo;
}

// ---------------- mma.sync 3-pass fp16 GEMM (z-fused, unchanged) ---------------
#define BKH     32
#define MAT_B   (128*64)
#define STAGE_B (4*MAT_B)
#define NSTAGE  4
#define GEMM_SMEM (NSTAGE*STAGE_B)  // 131072

template <int MODE>
__global__ __launch_bounds__(512, 1) void gemm_mma_split(
    const __half* __restrict__ Ahi, const __half* __restrict__ Alo,
    const __half* __restrict__ Wh0, const __half* __restrict__ Wl0,
    const __half* __restrict__ Wh1, const __half* __restrict__ Wl1,
    const __half* __restrict__ Wh2, const __half* __restrict__ Wl2,
    const float* __restrict__ b0p, const float* __restrict__ b1p,
    const float* __restrict__ b2p,
    float* __restrict__ C,
    __half* __restrict__ C0, __half* __restrict__ C1, __half* __restrict__ C2)
{
    const __half* Whi; const __half* Wlo; const float* bias; __half* Ch;
    if      (blockIdx.z == 0) { Whi = Wh0; Wlo = Wl0; bias = b0p; Ch = C0; }
    else if (blockIdx.z == 1) { Whi = Wh1; Wlo = Wl1; bias = b1p; Ch = C1; }
    else                      { Whi = Wh2; Wlo = Wl2; bias = b2p; Ch = C2; }

    extern __shared__ __align__(1024) char smraw[];
    const uint32_t sb = smem_u32(smraw);

    const int tid = threadIdx.x;
    const int wid = tid >> 5;
    const int l   = tid & 31;
    const int wm  = wid & 3;
    const int wn  = wid >> 2;
    const int m0  = blockIdx.y * 128;
    const int n0  = blockIdx.x * 128;

    const int crow = tid >> 2;
    const int cch  = tid & 3;
    const uint32_t sst = (uint32_t)(crow * 64 + ((cch ^ ((crow >> 1) & 3)) << 4));
    const __half* gAh = Ahi + (size_t)(m0 + crow) * D_ + cch * 8;
    const __half* gAl = Alo + (size_t)(m0 + crow) * D_ + cch * 8;
    const __half* gWh = Whi + (size_t)(n0 + crow) * D_ + cch * 8;
    const __half* gWl = Wlo + (size_t)(n0 + crow) * D_ + cch * 8;

    const int rA  = wm * 32 + (l & 15);
    const int xkA = (rA >> 1) & 3;
    const int cA  = l >> 4;
    const uint32_t aA_k0 = (uint32_t)(rA * 64 + ((cA       ^ xkA) << 4));
    const uint32_t aA_k1 = (uint32_t)(rA * 64 + (((cA + 2) ^ xkA) << 4));
    const int rB  = wn * 32 + (l & 7) + ((l >> 4) << 3);
    const int xkB = (rB >> 1) & 3;
    const int cB  = (l >> 3) & 1;
    const uint32_t aB_k0 = (uint32_t)(rB * 64 + ((cB       ^ xkB) << 4));
    const uint32_t aB_k1 = (uint32_t)(rB * 64 + (((cB + 2) ^ xkB) << 4));

    float acc[2][4][4];
#pragma unroll
    for (int mt = 0; mt < 2; mt++)
#pragma unroll
        for (int nt = 0; nt < 4; nt++)
#pragma unroll
            for (int e = 0; e < 4; e++) acc[mt][nt][e] = 0.f;

    const int NKT = D_ / BKH;

    auto issue_stage = [&](int s) {
        const uint32_t d = sb + (s & (NSTAGE-1)) * STAGE_B + sst;
        const int off = s * BKH;
        cp_async16(d + 0*MAT_B, gAh + off);
        cp_async16(d + 1*MAT_B, gAl + off);
        cp_async16(d + 2*MAT_B, gWh + off);
        cp_async16(d + 3*MAT_B, gWl + off);
    };

    issue_stage(0); CP_COMMIT();
    issue_stage(1); CP_COMMIT();
    issue_stage(2); CP_COMMIT();

    for (int kt = 0; kt < NKT; kt++) {
        if (kt + 3 < NKT) issue_stage(kt + 3);
        CP_COMMIT();
        CP_WAIT(3);
        __syncthreads();

        const uint32_t base = sb + (kt & (NSTAGE-1)) * STAGE_B;

#pragma unroll
        for (int kk = 0; kk < 2; kk++) {
            const uint32_t aA = base + (kk ? aA_k1 : aA_k0);
            const uint32_t aB = base + (kk ? aB_k1 : aB_k0);

            uint32_t ah[2][4];
            ldsm_x4(ah[0], aA + 0*MAT_B);
            ldsm_x4(ah[1], aA + 0*MAT_B + 1024);
            uint32_t wh[2][4];
            ldsm_x4(wh[0], aB + 2*MAT_B);
            ldsm_x4(wh[1], aB + 2*MAT_B + 1024);
#pragma unroll
            for (int mt = 0; mt < 2; mt++)
#pragma unroll
                for (int nt = 0; nt < 4; nt++)
                    mma_f16(acc[mt][nt], ah[mt], &wh[nt >> 1][(nt & 1) * 2]);

            uint32_t wl[2][4];
            ldsm_x4(wl[0], aB + 3*MAT_B);
            ldsm_x4(wl[1], aB + 3*MAT_B + 1024);
#pragma unroll
            for (int mt = 0; mt < 2; mt++)
#pragma unroll
                for (int nt = 0; nt < 4; nt++)
                    mma_f16(acc[mt][nt], ah[mt], &wl[nt >> 1][(nt & 1) * 2]);

            uint32_t al[2][4];
            ldsm_x4(al[0], aA + 1*MAT_B);
            ldsm_x4(al[1], aA + 1*MAT_B + 1024);
#pragma unroll
            for (int mt = 0; mt < 2; mt++)
#pragma unroll
                for (int nt = 0; nt < 4; nt++)
                    mma_f16(acc[mt][nt], al[mt], &wh[nt >> 1][(nt & 1) * 2]);
        }

        __syncthreads();
    }

    const int rbase = m0 + wm*32 + (l >> 2);
    const int cbase = n0 + wn*32 + (l & 3) * 2;
#pragma unroll
    for (int mt = 0; mt < 2; mt++) {
#pragma unroll
        for (int nt = 0; nt < 4; nt++) {
            const int col = cbase + nt * 8;
            const float b0 = bias[col], b1 = bias[col + 1];
            const size_t r0o = (size_t)(rbase + mt*16) * D_ + col;
            const size_t r1o = (size_t)(rbase + mt*16 + 8) * D_ + col;
            if (MODE == 1) {
                *(uint32_t*)(Ch + r0o) = pack2h(acc[mt][nt][0] + b0, acc[mt][nt][1] + b1);
                *(uint32_t*)(Ch + r1o) = pack2h(acc[mt][nt][2] + b0, acc[mt][nt][3] + b1);
            } else {
                float2 v0 = { acc[mt][nt][0] + b0, acc[mt][nt][1] + b1 };
                float2 v1 = { acc[mt][nt][2] + b0, acc[mt][nt][3] + b1 };
                *(float2*)(C + r0o) = v0;
                *(float2*)(C + r1o) = v1;
            }
        }
    }
}

// ---------------- fp16 flash attention, P in registers -------------------------
// 128 queries/CTA, 8 warps x 16 q-rows. QK accumulator fragments are reused
// DIRECTLY as PV A-fragments (no P smem round-trip). Base-2 softmax with
// additive mask fold (mask smem holds 0 / -1e30).
#define AT_QP 72
#define oQ 0
#define oK 18432
#define oV 36864
#define oM 55296
#define ATT_SMEM (oM + S_*4)   // 63488

__global__ __launch_bounds__(256, 2) void attn_mma(
    const __half* __restrict__ Qh, const __half* __restrict__ Kh,
    const __half* __restrict__ Vh, const int* __restrict__ mask,
    __half* __restrict__ Ah, __half* __restrict__ Al)
{
    extern __shared__ __align__(1024) char sm[];
    const uint32_t sb = smem_u32(sm);
    float* Mskf = (float*)(sm + oM);

    const int tid = threadIdx.x;
    const int wid = tid >> 5;
    const int l   = tid & 31;
    const int b   = blockIdx.y >> 4;
    const int h   = blockIdx.y & 15;
    const int q0  = blockIdx.x * 128;

    const int crow = tid >> 1, chc = (tid & 1) * 32;
    const uint32_t cds = (uint32_t)(crow * AT_QP + chc) * 2;
    const size_t gKVrow = (size_t)(b*S_ + crow) * D_ + h*DH_ + chc;

    auto issue_K = [&](int kt) {
        const size_t g = gKVrow + (size_t)kt * 128 * D_;
#pragma unroll
        for (int j = 0; j < 4; j++)
            cp_async16(sb + oK + cds + j*16, Kh + g + j*8);
    };
    auto issue_V = [&](int kt) {
        const size_t g = gKVrow + (size_t)kt * 128 * D_;
#pragma unroll
        for (int j = 0; j < 4; j++)
            cp_async16(sb + oV + cds + j*16, Vh + g + j*8);
    };

    // additive mask: 0 (keep) / -1e30 (drop)
    for (int i = tid; i < S_; i += 256)
        Mskf[i] = mask[(size_t)b*S_ + i] ? 0.f : -1e30f;

    {
        const size_t g = (size_t)(b*S_ + q0 + crow) * D_ + h*DH_ + chc;
#pragma unroll
        for (int j = 0; j < 4; j++)
            cp_async16(sb + oQ + cds + j*16, Qh + g + j*8);
    }
    issue_K(0);
    CP_COMMIT();
    issue_V(0);
    CP_COMMIT();

    float m_run[2] = { -1e30f, -1e30f };
    float l_run[2] = { 0.f, 0.f };
    float o[8][4];
#pragma unroll
    for (int nt = 0; nt < 8; nt++)
#pragma unroll
        for (int e = 0; e < 4; e++) o[nt][e] = 0.f;

    const uint32_t aQ  = sb + oQ + (uint32_t)(((wid<<4) + (l & 15)) * AT_QP + ((l >> 4) << 3)) * 2;
    const uint32_t aKo = (uint32_t)(((l & 7) + ((l >> 4) << 3)) * AT_QP + (((l >> 3) & 1) << 3)) * 2;
    const uint32_t aVo = (uint32_t)(((l & 7) + (((l >> 3) & 1) << 3)) * AT_QP + ((l >> 4) << 3)) * 2;

    const int c0 = (l & 3) * 2;
    const float KSC = 0.125f * 1.44269504f;   // scale * log2(e)

    for (int kt = 0; kt < S_/128; kt++) {
        CP_WAIT(1);            // K_kt (+Q first iter) ready
        __syncthreads();

        // ---- QK^T (single pass): s[16][4] ----
        float s[16][4];
#pragma unroll
        for (int nt = 0; nt < 16; nt++)
#pragma unroll
            for (int e = 0; e < 4; e++) s[nt][e] = 0.f;

#pragma unroll
        for (int ks = 0; ks < 4; ks++) {
            uint32_t q[4];
            ldsm_x4(q, aQ + ks*32);
#pragma unroll
            for (int np = 0; np < 8; np++) {
                uint32_t k[4];
                ldsm_x4(k, sb + oK + aKo + np*(16*AT_QP*2) + ks*32);
                mma_f16(s[2*np],   q, k);
                mma_f16(s[2*np+1], q, k+2);
            }
        }

        // ---- additive mask + base-2 scale + online softmax ----
        const int kb = kt * 128;
        float mx0 = -1e30f, mx1 = -1e30f;
#pragma unroll
        for (int nt = 0; nt < 16; nt++) {
            const float mb0 = Mskf[kb + nt*8 + c0];
            const float mb1 = Mskf[kb + nt*8 + c0 + 1];
            s[nt][0] = fmaf(s[nt][0], KSC, mb0);
            s[nt][1] = fmaf(s[nt][1], KSC, mb1);
            s[nt][2] = fmaf(s[nt][2], KSC, mb0);
            s[nt][3] = fmaf(s[nt][3], KSC, mb1);
            mx0 = fmaxf(mx0, fmaxf(s[nt][0], s[nt][1]));
            mx1 = fmaxf(mx1, fmaxf(s[nt][2], s[nt][3]));
        }
        mx0 = fmaxf(mx0, __shfl_xor_sync(0xffffffffu, mx0, 1));
        mx0 = fmaxf(mx0, __shfl_xor_sync(0xffffffffu, mx0, 2));
        mx1 = fmaxf(mx1, __shfl_xor_sync(0xffffffffu, mx1, 1));
        mx1 = fmaxf(mx1, __shfl_xor_sync(0xffffffffu, mx1, 2));

        const float mn0 = fmaxf(m_run[0], mx0);
        const float mn1 = fmaxf(m_run[1], mx1);
        const float al0 = ex2f(m_run[0] - mn0);
        const float al1 = ex2f(m_run[1] - mn1);
        m_run[0] = mn0; m_run[1] = mn1;

        float su0 = 0.f, su1 = 0.f;
#pragma unroll
        for (int nt = 0; nt < 16; nt++) {
            s[nt][0] = ex2f(s[nt][0] - mn0);
            s[nt][1] = ex2f(s[nt][1] - mn0);
            s[nt][2] = ex2f(s[nt][2] - mn1);
            s[nt][3] = ex2f(s[nt][3] - mn1);
            su0 += s[nt][0] + s[nt][1];
            su1 += s[nt][2] + s[nt][3];
        }
        su0 += __shfl_xor_sync(0xffffffffu, su0, 1);
        su0 += __shfl_xor_sync(0xffffffffu, su0, 2);
        su1 += __shfl_xor_sync(0xffffffffu, su1, 1);
        su1 += __shfl_xor_sync(0xffffffffu, su1, 2);
        l_run[0] = l_run[0] * al0 + su0;
        l_run[1] = l_run[1] * al1 + su1;

#pragma unroll
        for (int nt = 0; nt < 8; nt++) {
            o[nt][0] *= al0; o[nt][1] *= al0;
            o[nt][2] *= al1; o[nt][3] *= al1;
        }

        CP_WAIT(0);            // V_kt arrived
        __syncthreads();       // all warps done reading K_kt; V visible

        if (kt + 1 < S_/128) issue_K(kt + 1);   // overlaps PV
        CP_COMMIT();

        // ---- PV: P fed straight from registers (QK C-frag == PV A-frag) ----
#pragma unroll
        for (int ks = 0; ks < 8; ks++) {
            uint32_t p[4];
            p[0] = pack2h(s[2*ks][0],   s[2*ks][1]);    // row r0,   k-lo
            p[1] = pack2h(s[2*ks][2],   s[2*ks][3]);    // row r0+8, k-lo
            p[2] = pack2h(s[2*ks+1][0], s[2*ks+1][1]);  // row r0,   k-hi
            p[3] = pack2h(s[2*ks+1][2], s[2*ks+1][3]);  // row r0+8, k-hi
#pragma unroll
            for (int vb = 0; vb < 4; vb++) {
                uint32_t v[4];
                ldsm_x4t(v, sb + oV + aVo + ks*(16*AT_QP*2) + vb*32);
                mma_f16(o[2*vb],   p, v);
                mma_f16(o[2*vb+1], p, v+2);
            }
        }

        __syncthreads();       // V_kt reads done
        if (kt + 1 < S_/128) issue_V(kt + 1);   // overlaps next QK
        CP_COMMIT();
    }

    // ---- epilogue: normalize, split to fp16 hi/lo ----
    const float i0 = 1.f / l_run[0];
    const float i1 = 1.f / l_run[1];
    const size_t row0 = (size_t)(b*S_ + q0 + (wid<<4) + (l >> 2));
    const size_t row1 = row0 + 8;
#pragma unroll
    for (int nt = 0; nt < 8; nt++) {
        const int col = h*DH_ + nt*8 + c0;
        uint32_t hi, lo;
        split2h(o[nt][0]*i0, o[nt][1]*i0, hi, lo);
        *(uint32_t*)(Ah + row0*D_ + col) = hi;
        *(uint32_t*)(Al + row0*D_ + col) = lo;
        split2h(o[nt][2]*i1, o[nt][3]*i1, hi, lo);
        *(uint32_t*)(Ah + row1*D_ + col) = hi;
        *(uint32_t*)(Al + row1*D_ + col) = lo;
    }
}

// ---------------------------------------------------------------------------
extern "C" void kernel_launch(void* const* d_in, const int* in_sizes, int n_in,
                              void* d_out, int out_size)
{
    const float* x    = (const float*)d_in[0];
    const int*   mask = (const int*)  d_in[1];
    const float* Wq   = (const float*)d_in[2];
    const float* bq   = (const float*)d_in[3];
    const float* Wk   = (const float*)d_in[4];
    const float* bk   = (const float*)d_in[5];
    const float* Wv   = (const float*)d_in[6];
    const float* bv   = (const float*)d_in[7];
    const float* Wo   = (const float*)d_in[8];
    const float* bo   = (const float*)d_in[9];
    float* out = (float*)d_out;

    __half *xhi, *xlo, *qh, *kh, *vh, *ahi, *alo;
    __half *wqh, *wql, *wkh, *wkl, *wvh, *wvl, *woh, *wol;
    cudaGetSymbolAddress((void**)&xhi, g_xhi);
    cudaGetSymbolAddress((void**)&xlo, g_xlo);
    cudaGetSymbolAddress((void**)&qh,  g_qh);
    cudaGetSymbolAddress((void**)&kh,  g_kh);
    cudaGetSymbolAddress((void**)&vh,  g_vh);
    cudaGetSymbolAddress((void**)&ahi, g_ahi);
    cudaGetSymbolAddress((void**)&alo, g_alo);
    cudaGetSymbolAddress((void**)&wqh, g_wqhi);
    cudaGetSymbolAddress((void**)&wql, g_wqlo);
    cudaGetSymbolAddress((void**)&wkh, g_wkhi);
    cudaGetSymbolAddress((void**)&wkl, g_wklo);
    cudaGetSymbolAddress((void**)&wvh, g_wvhi);
    cudaGetSymbolAddress((void**)&wvl, g_wvlo);
    cudaGetSymbolAddress((void**)&woh, g_wohi);
    cudaGetSymbolAddress((void**)&wol, g_wolo);

    cudaFuncSetAttribute(gemm_mma_split<0>,
                         cudaFuncAttributeMaxDynamicSharedMemorySize, GEMM_SMEM);
    cudaFuncSetAttribute(gemm_mma_split<1>,
                         cudaFuncAttributeMaxDynamicSharedMemorySize, GEMM_SMEM);
    cudaFuncSetAttribute(attn_mma,
                         cudaFuncAttributeMaxDynamicSharedMemorySize, ATT_SMEM);

    conv_split<<<(M_*D_/4)/256, 256>>>(x, xhi, xlo, M_*D_/4);
    dim3 gw((D_*D_/4)/256, 4);
    conv_split_w<<<gw, 256>>>(Wq, Wk, Wv, Wo,
                              wqh, wql, wkh, wkl, wvh, wvl, woh, wol);

    dim3 gq(D_/128, M_/128, 3);   // fused QKV
    gemm_mma_split<1><<<gq, 512, GEMM_SMEM>>>(
        xhi, xlo,
        wqh, wql, wkh, wkl, wvh, wvl,
        bq, bk, bv,
        nullptr, qh, kh, vh);

    dim3 ga(S_/128, B_*H_);    // (16, 32)
    attn_mma<<<ga, 256, ATT_SMEM>>>(qh, kh, vh, mask, ahi, alo);

    dim3 gg(D_/128, M_/128, 1);
    gemm_mma_split<0><<<gg, 512, GEMM_SMEM>>>(
        ahi, alo,
        woh, wol, woh, wol, woh, wol,
        bo, bo, bo,
        out, nullptr, nullptr, nullptr);
}